// round 14
// baseline (speedup 1.0000x reference)
#include <cuda_runtime.h>

#define NB 8
#define NA 65536
#define NG 32
#define NC 16                 // cells per dimension
#define NCELL (NC * NC)       // 256
#define HEXT 0.1501f          // max anchor half-extent (a_wh < 0.3) + slack

// Scratch (no allocations allowed)
__device__ unsigned g_hist[NCELL];
__device__ unsigned g_off[NCELL];
__device__ unsigned g_cur[NCELL];
__device__ float4   g_ba[NA];            // binned anchors (xyxy)
__device__ float    g_bsa[NA];           // binned anchor areas
__device__ unsigned g_bix[NA];           // binned original indices
__device__ unsigned long long g_best[NB * NG];   // (iou_bits<<32)|~idx
__device__ unsigned long long g_plist[NB][NA];   // (word<<32)|aix
__device__ int      g_np[NB];
__device__ float    g_class;
__device__ float    g_coord[NB];
__device__ float    g_cntf[NB];
__device__ int      g_tickF;

__device__ __forceinline__ float focal(float p) {
    float o = 1.f - p; return o * o * (-__logf(p));
}

// ---- k1: cell histogram + global focal(c0) sum + g_best init ----
__global__ __launch_bounds__(256) void kHist(
    const float4* __restrict__ anchors, const float2* __restrict__ cls)
{
    const int tid = threadIdx.x, a = blockIdx.x * 256 + tid;
    __shared__ unsigned sh[NCELL];
    __shared__ float    rs[8];
    sh[tid] = 0u;
    if (blockIdx.x == 0 && tid < NB * NG) g_best[tid] = 0xFFFFFFFFull; // iou=0, idx=0
    __syncthreads();

    float4 q = __ldg(anchors + a);
    int cx = min(NC - 1, max(0, (int)((q.x + q.z) * (0.5f * NC))));
    int cy = min(NC - 1, max(0, (int)((q.y + q.w) * (0.5f * NC))));
    atomicAdd(&sh[cy * NC + cx], 1u);

    float cs = 0.f;
#pragma unroll
    for (int b = 0; b < NB; b++) {
        float2 c = __ldg(&cls[b * NA + a]);
        cs += focal(c.x);
    }
#pragma unroll
    for (int o = 16; o; o >>= 1) cs += __shfl_down_sync(0xffffffffu, cs, o);
    if ((tid & 31) == 0) rs[tid >> 5] = cs;
    __syncthreads();
    if (sh[tid]) atomicAdd(&g_hist[tid], sh[tid]);
    if (tid == 0) {
        float t = 0.f;
#pragma unroll
        for (int w = 0; w < 8; w++) t += rs[w];
        atomicAdd(&g_class, t);
    }
}

// ---- k2: scan (redundant per block) + scatter anchors into bins ----
__global__ __launch_bounds__(256) void kScatter(const float4* __restrict__ anchors)
{
    const int tid = threadIdx.x, a = blockIdx.x * 256 + tid;
    __shared__ unsigned s[NCELL], se[NCELL];
    unsigned h = g_hist[tid];
    s[tid] = h; __syncthreads();
    for (int d = 1; d < NCELL; d <<= 1) {
        unsigned v = (tid >= d) ? s[tid - d] : 0u;
        __syncthreads(); s[tid] += v; __syncthreads();
    }
    se[tid] = s[tid] - h;          // exclusive offset
    __syncthreads();
    if (blockIdx.x == 0) g_off[tid] = se[tid];

    float4 q = __ldg(anchors + a);
    int cx = min(NC - 1, max(0, (int)((q.x + q.z) * (0.5f * NC))));
    int cy = min(NC - 1, max(0, (int)((q.y + q.w) * (0.5f * NC))));
    int cell = cy * NC + cx;
    unsigned p = atomicAdd(&g_cur[cell], 1u);
    unsigned dst = se[cell] + p;
    g_ba[dst]  = q;
    g_bsa[dst] = (q.z - q.x) * (q.w - q.y);
    g_bix[dst] = (unsigned)a;
}

// ---- k3: sparse pair evaluation over candidate (cell, gt) pairs ----
__global__ __launch_bounds__(256) void kPairs(
    const float* __restrict__ gt, const int* __restrict__ nobj)
{
    const int tid = threadIdx.x, lane = tid & 31, warp = tid >> 5;
    const int cell = blockIdx.x & (NCELL - 1), b = blockIdx.x >> 8;
    const int ccx = cell & (NC - 1), ccy = cell >> 4;
    const int n = __ldg(nobj + b);

    __shared__ float sx1[NG], sy1[NG], sx2[NG], sy2[NG], ssg[NG];
    __shared__ int   s_gl[NG];
    __shared__ int   s_m;

    if (tid < NG) {
        float4 q = ((const float4*)gt)[b * NG + tid];
        float hx = q.z * 0.5f, hy = q.w * 0.5f;
        float x1 = q.x - hx, y1 = q.y - hy, x2 = q.x + hx, y2 = q.y + hy;
        sx1[tid] = x1; sy1[tid] = y1; sx2[tid] = x2; sy2[tid] = y2;
        ssg[tid] = (x2 - x1) * (y2 - y1);
    }
    if (warp == 0) {
        bool rel = false;
        if (lane < n) {
            float4 q = ((const float4*)gt)[b * NG + lane];
            float hx = q.z * 0.5f, hy = q.w * 0.5f;
            int x0 = max(0,      (int)floorf((q.x - hx - HEXT) * NC));
            int x1 = min(NC - 1, (int)floorf((q.x + hx + HEXT) * NC));
            int y0 = max(0,      (int)floorf((q.y - hy - HEXT) * NC));
            int y1 = min(NC - 1, (int)floorf((q.y + hy + HEXT) * NC));
            rel = (ccx >= x0) && (ccx <= x1) && (ccy >= y0) && (ccy <= y1);
        }
        unsigned bal = __ballot_sync(0xffffffffu, rel);
        if (rel) s_gl[__popc(bal & ((1u << lane) - 1u))] = lane;
        if (lane == 0) s_m = __popc(bal);
    }
    __syncthreads();
    const int m = s_m;
    if (m == 0) return;

    const unsigned off = g_off[cell], cnt = g_hist[cell];

    for (unsigned base = 0; base < cnt; base += 256) {
        const unsigned i = base + tid;
        const bool v = i < cnt;
        float4 A; float sa; unsigned aix;
        if (v) { A = g_ba[off + i]; sa = g_bsa[off + i]; aix = g_bix[off + i]; }
        else   { A = make_float4(3e9f, 3e9f, 3e9f, 3e9f); sa = 0.f; aix = 0xFFFFFFFFu; }

        unsigned word = 0u;
        for (int j = 0; j < m; j++) {
            const int g = s_gl[j];
            float lx = fmaxf(A.x, sx1[g]), ly = fmaxf(A.y, sy1[g]);
            float rx = fminf(A.z, sx2[g]), ry = fminf(A.w, sy2[g]);
            float w = fmaxf(rx - lx, 0.f), h = fmaxf(ry - ly, 0.f);
            float inter = w * h;
            float u = (sa + ssg[g]) - inter;
            // exact sign of inter - 0.5u (single rounding; 0.5u exact)
            if (fmaf(-0.5f, u, inter) > 0.f) word |= 1u << g;
            // per-gt warp argmax (skip if no lane overlaps)
            if (__any_sync(0xffffffffu, inter > 0.f)) {
                float bi = inter, bu = u; unsigned bx = aix;
#pragma unroll
                for (int o = 16; o; o >>= 1) {
                    float    oi = __shfl_down_sync(0xffffffffu, bi, o);
                    float    ou = __shfl_down_sync(0xffffffffu, bu, o);
                    unsigned ox = __shfl_down_sync(0xffffffffu, bx, o);
                    float Aa = oi * bu, Cc = bi * ou;
                    if (Aa > Cc || (Aa == Cc && ox < bx)) { bi = oi; bu = ou; bx = ox; }
                }
                if (lane == 0 && bi > 0.f) {
                    float iou = __fdiv_rn(bi, bu);   // matches reference rounding
                    unsigned long long key =
                        ((unsigned long long)__float_as_uint(iou) << 32) | (unsigned)(~bx);
                    atomicMax(&g_best[b * NG + g], key);
                }
            }
        }
        if (v && word) {
            int p = atomicAdd(&g_np[b], 1);
            g_plist[b][p] = ((unsigned long long)word << 32) | aix;
        }
    }
}

// ---- k4: per-batch finalize (list + forced corrections), output, reset ----
__global__ __launch_bounds__(256) void kFinal(
    const float4* __restrict__ boxes, const float2* __restrict__ cls,
    const float4* __restrict__ anchors, const float* __restrict__ gt,
    const int* __restrict__ nobj, float* __restrict__ out)
{
    const int b = blockIdx.x, tid = threadIdx.x;
    const int lane = tid & 31, warp = tid >> 5;
    const int n = __ldg(nobj + b);

    __shared__ float sx1[NG], sy1[NG], sx2[NG], sy2[NG], ssg[NG];
    __shared__ float r1[8], r2[8], r3[8];
    __shared__ bool  s_last;

    if (tid < NG) {
        float4 q = ((const float4*)gt)[b * NG + tid];
        float hx = q.z * 0.5f, hy = q.w * 0.5f;
        float x1 = q.x - hx, y1 = q.y - hy, x2 = q.x + hx, y2 = q.y + hy;
        sx1[tid] = x1; sy1[tid] = y1; sx2[tid] = x2; sy2[tid] = y2;
        ssg[tid] = (x2 - x1) * (y2 - y1);
    }
    __syncthreads();

    const int np = g_np[b];
    float cc = 0.f, crd = 0.f, cnt = 0.f;

    for (int r = tid; r < np; r += 256) {
        unsigned long long rec = g_plist[b][r];
        unsigned aix  = (unsigned)rec;
        unsigned word = (unsigned)(rec >> 32);
        float2 c = __ldg(&cls[b * NA + aix]);
        cc += focal(c.y) - focal(c.x);
        float4 qb = __ldg(&boxes[b * NA + aix]);
        do {
            int g = __ffs(word) - 1; word &= word - 1;
            crd += fabsf(qb.x - sx1[g]) + fabsf(qb.y - sy1[g])
                 + fabsf(qb.z - sx2[g]) + fabsf(qb.w - sy2[g]);
            cnt += 1.f;
        } while (word);
    }

    if (tid < n) {                          // forced corrections, one thread per gt
        unsigned long long k = g_best[b * NG + tid];
        unsigned fx = ~(unsigned)k;
        float4 qa = __ldg(anchors + fx);
        float sa = (qa.z - qa.x) * (qa.w - qa.y);
        unsigned w2 = 0u;
        for (int g2 = 0; g2 < n; g2++) {
            float lx = fmaxf(qa.x, sx1[g2]), ly = fmaxf(qa.y, sy1[g2]);
            float rx = fminf(qa.z, sx2[g2]), ry = fminf(qa.w, sy2[g2]);
            float w = fmaxf(rx - lx, 0.f), h = fmaxf(ry - ly, 0.f);
            float inter = w * h, u = (sa + ssg[g2]) - inter;
            if (fmaf(-0.5f, u, inter) > 0.f) w2 |= 1u << g2;
        }
        if (!((w2 >> tid) & 1u)) {          // forced pair not already counted
            float4 qb = __ldg(&boxes[b * NA + fx]);
            crd += fabsf(qb.x - sx1[tid]) + fabsf(qb.y - sy1[tid])
                 + fabsf(qb.z - sx2[tid]) + fabsf(qb.w - sy2[tid]);
            cnt += 1.f;
        }
        if (w2 == 0u) {                     // anchor was negative in global sum
            bool first = true;              // dedupe: smallest g forcing this anchor
            for (int g2 = 0; g2 < tid; g2++)
                if ((~(unsigned)g_best[b * NG + g2]) == fx) first = false;
            if (first) {
                float2 c = __ldg(&cls[b * NA + fx]);
                cc += focal(c.y) - focal(c.x);
            }
        }
    }

#pragma unroll
    for (int o = 16; o; o >>= 1) {
        cc  += __shfl_down_sync(0xffffffffu, cc, o);
        crd += __shfl_down_sync(0xffffffffu, crd, o);
        cnt += __shfl_down_sync(0xffffffffu, cnt, o);
    }
    if (lane == 0) { r1[warp] = cc; r2[warp] = crd; r3[warp] = cnt; }
    __syncthreads();
    if (tid == 0) {
        float tc = 0.f, tr = 0.f, tn = 0.f;
#pragma unroll
        for (int w = 0; w < 8; w++) { tc += r1[w]; tr += r2[w]; tn += r3[w]; }
        atomicAdd(&g_class, tc);
        g_coord[b] = tr; g_cntf[b] = tn;
        __threadfence();
        s_last = (atomicAdd(&g_tickF, 1) == NB - 1);
    }
    __syncthreads();
    if (s_last) {
        // reset scratch for next graph replay
        if (tid < NCELL) { g_hist[tid] = 0u; g_cur[tid] = 0u; }
        if (tid < NB) g_np[tid] = 0;
        if (tid == 0) {
            __threadfence();
            float coord = 0.f;
#pragma unroll
            for (int bb = 0; bb < NB; bb++)
                coord += (*(volatile float*)&g_coord[bb])
                       / (4.f * (*(volatile float*)&g_cntf[bb]));
            float cl = (*(volatile float*)&g_class) * (0.01f / 8.f);
            float co = coord * (1.0f / 8.f);
            out[0] = cl + co; out[1] = cl; out[2] = co;
            g_class = 0.f; g_tickF = 0;
        }
    }
}

extern "C" void kernel_launch(void* const* d_in, const int* in_sizes, int n_in,
                              void* d_out, int out_size) {
    const float* boxes   = (const float*)d_in[0];   // [8,65536,4]
    const float* classes = (const float*)d_in[1];   // [8,65536,2]
    const float* anchors = (const float*)d_in[2];   // [65536,4] xyxy
    const float* gt      = (const float*)d_in[3];   // [8,32,4] xywh
    const int*   nobj    = (const int*)d_in[4];     // [8]
    float* out = (float*)d_out;

    kHist   <<<NA / 256, 256>>>((const float4*)anchors, (const float2*)classes);
    kScatter<<<NA / 256, 256>>>((const float4*)anchors);
    kPairs  <<<NB * NCELL, 256>>>(gt, nobj);
    kFinal  <<<NB, 256>>>((const float4*)boxes, (const float2*)classes,
                          (const float4*)anchors, gt, nobj, out);
}

// round 15
// speedup vs baseline: 1.1156x; 1.1156x over previous
#include <cuda_runtime.h>

#define NB 8
#define NA 65536
#define NG 32
#define NC 16                 // cells per dimension
#define NCELL (NC * NC)       // 256
#define HEXT 0.1501f          // max anchor half-extent (a_wh < 0.3) + slack

// Scratch (no allocations allowed)
__device__ unsigned g_hist[NCELL];
__device__ unsigned g_off[NCELL];
__device__ unsigned g_cur[NCELL];
__device__ float4   g_ba[NA];            // binned anchors (xyxy)
__device__ float    g_bsa[NA];           // binned anchor areas
__device__ unsigned g_bix[NA];           // binned original indices
__device__ unsigned long long g_best[NB * NG];   // (iou_bits<<32)|~idx
__device__ float    g_class;
__device__ float    g_coord[NB];
__device__ float    g_cntf[NB];
__device__ int      g_tickF;

__device__ __forceinline__ float focal(float p) {
    float o = 1.f - p; return o * o * (-__logf(p));
}

// ---- k1: cell histogram + global focal(c0) sum + g_best init ----
__global__ __launch_bounds__(256) void kHist(
    const float4* __restrict__ anchors, const float2* __restrict__ cls)
{
    const int tid = threadIdx.x, a = blockIdx.x * 256 + tid;
    __shared__ unsigned sh[NCELL];
    __shared__ float    rs[8];
    sh[tid] = 0u;
    if (blockIdx.x == 0 && tid < NB * NG) g_best[tid] = 0xFFFFFFFFull; // iou=0, idx=0
    __syncthreads();

    float4 q = __ldg(anchors + a);
    int cx = min(NC - 1, max(0, (int)((q.x + q.z) * (0.5f * NC))));
    int cy = min(NC - 1, max(0, (int)((q.y + q.w) * (0.5f * NC))));
    atomicAdd(&sh[cy * NC + cx], 1u);

    float cs = 0.f;
#pragma unroll
    for (int b = 0; b < NB; b++) {
        float2 c = __ldg(&cls[b * NA + a]);
        cs += focal(c.x);
    }
#pragma unroll
    for (int o = 16; o; o >>= 1) cs += __shfl_down_sync(0xffffffffu, cs, o);
    if ((tid & 31) == 0) rs[tid >> 5] = cs;
    __syncthreads();
    if (sh[tid]) atomicAdd(&g_hist[tid], sh[tid]);
    if (tid == 0) {
        float t = 0.f;
#pragma unroll
        for (int w = 0; w < 8; w++) t += rs[w];
        atomicAdd(&g_class, t);
    }
}

// ---- k2: scan (redundant per block) + scatter anchors into bins ----
__global__ __launch_bounds__(256) void kScatter(const float4* __restrict__ anchors)
{
    const int tid = threadIdx.x, a = blockIdx.x * 256 + tid;
    __shared__ unsigned s[NCELL], se[NCELL];
    unsigned h = g_hist[tid];
    s[tid] = h; __syncthreads();
    for (int d = 1; d < NCELL; d <<= 1) {
        unsigned v = (tid >= d) ? s[tid - d] : 0u;
        __syncthreads(); s[tid] += v; __syncthreads();
    }
    se[tid] = s[tid] - h;          // exclusive offset
    __syncthreads();
    if (blockIdx.x == 0) g_off[tid] = se[tid];

    float4 q = __ldg(anchors + a);
    int cx = min(NC - 1, max(0, (int)((q.x + q.z) * (0.5f * NC))));
    int cy = min(NC - 1, max(0, (int)((q.y + q.w) * (0.5f * NC))));
    int cell = cy * NC + cx;
    unsigned p = atomicAdd(&g_cur[cell], 1u);
    unsigned dst = se[cell] + p;
    g_ba[dst]  = q;
    g_bsa[dst] = (q.z - q.x) * (q.w - q.y);
    g_bix[dst] = (unsigned)a;
}

// ---- k3: sparse pair eval; positives processed INLINE ----
__global__ __launch_bounds__(256) void kPairs(
    const float4* __restrict__ boxes, const float2* __restrict__ cls,
    const float* __restrict__ gt, const int* __restrict__ nobj)
{
    const int tid = threadIdx.x, lane = tid & 31, warp = tid >> 5;
    const int cell = blockIdx.x & (NCELL - 1), b = blockIdx.x >> 8;
    const int ccx = cell & (NC - 1), ccy = cell >> 4;
    const int n = __ldg(nobj + b);

    __shared__ float sx1[NG], sy1[NG], sx2[NG], sy2[NG], ssg[NG];
    __shared__ int   s_gl[NG];
    __shared__ int   s_m;
    __shared__ float r1[8], r2[8], r3[8];

    if (tid < NG) {
        float4 q = ((const float4*)gt)[b * NG + tid];
        float hx = q.z * 0.5f, hy = q.w * 0.5f;
        float x1 = q.x - hx, y1 = q.y - hy, x2 = q.x + hx, y2 = q.y + hy;
        sx1[tid] = x1; sy1[tid] = y1; sx2[tid] = x2; sy2[tid] = y2;
        ssg[tid] = (x2 - x1) * (y2 - y1);
    }
    if (warp == 0) {
        bool rel = false;
        if (lane < n) {
            float4 q = ((const float4*)gt)[b * NG + lane];
            float hx = q.z * 0.5f, hy = q.w * 0.5f;
            int x0 = max(0,      (int)floorf((q.x - hx - HEXT) * NC));
            int x1 = min(NC - 1, (int)floorf((q.x + hx + HEXT) * NC));
            int y0 = max(0,      (int)floorf((q.y - hy - HEXT) * NC));
            int y1 = min(NC - 1, (int)floorf((q.y + hy + HEXT) * NC));
            rel = (ccx >= x0) && (ccx <= x1) && (ccy >= y0) && (ccy <= y1);
        }
        unsigned bal = __ballot_sync(0xffffffffu, rel);
        if (rel) s_gl[__popc(bal & ((1u << lane) - 1u))] = lane;
        if (lane == 0) s_m = __popc(bal);
    }
    __syncthreads();
    const int m = s_m;
    if (m == 0) return;

    const unsigned off = g_off[cell], cnt = g_hist[cell];
    float cc = 0.f, crd = 0.f, pcnt = 0.f;

    for (unsigned base = 0; base < cnt; base += 256) {
        const unsigned i = base + tid;
        const bool v = i < cnt;
        float4 A; float sa; unsigned aix;
        if (v) { A = g_ba[off + i]; sa = g_bsa[off + i]; aix = g_bix[off + i]; }
        else   { A = make_float4(3e9f, 3e9f, 3e9f, 3e9f); sa = 0.f; aix = 0xFFFFFFFFu; }

        unsigned word = 0u;
        for (int j = 0; j < m; j++) {
            const int g = s_gl[j];
            float lx = fmaxf(A.x, sx1[g]), ly = fmaxf(A.y, sy1[g]);
            float rx = fminf(A.z, sx2[g]), ry = fminf(A.w, sy2[g]);
            float w = fmaxf(rx - lx, 0.f), h = fmaxf(ry - ly, 0.f);
            float inter = w * h;
            float u = (sa + ssg[g]) - inter;
            // exact sign of inter - 0.5u (single rounding; 0.5u exact)
            if (fmaf(-0.5f, u, inter) > 0.f) word |= 1u << g;
            // per-gt argmax via redux: rounded iou, smallest-index tie-break
            unsigned bits = __float_as_uint(__fdiv_rn(inter, u));   // iou >= 0
            unsigned umax = __reduce_max_sync(0xffffffffu, bits);
            if (umax > 0u) {
                unsigned cand = (bits == umax) ? aix : 0xFFFFFFFFu;
                unsigned amin = __reduce_min_sync(0xffffffffu, cand);
                if (lane == 0) {
                    unsigned long long key =
                        ((unsigned long long)umax << 32) | (unsigned)(~amin);
                    atomicMax(&g_best[b * NG + g], key);
                }
            }
        }
        if (v && word) {                    // positive anchor: process inline
            float2 c = __ldg(&cls[b * NA + aix]);
            cc += focal(c.y) - focal(c.x);
            float4 qb = __ldg(&boxes[b * NA + aix]);
            do {
                int g = __ffs(word) - 1; word &= word - 1;
                crd += fabsf(qb.x - sx1[g]) + fabsf(qb.y - sy1[g])
                     + fabsf(qb.z - sx2[g]) + fabsf(qb.w - sy2[g]);
                pcnt += 1.f;
            } while (word);
        }
    }

#pragma unroll
    for (int o = 16; o; o >>= 1) {
        cc   += __shfl_down_sync(0xffffffffu, cc, o);
        crd  += __shfl_down_sync(0xffffffffu, crd, o);
        pcnt += __shfl_down_sync(0xffffffffu, pcnt, o);
    }
    if (lane == 0) { r1[warp] = cc; r2[warp] = crd; r3[warp] = pcnt; }
    __syncthreads();
    if (tid == 0) {
        float tc = 0.f, tr = 0.f, tn = 0.f;
#pragma unroll
        for (int w = 0; w < 8; w++) { tc += r1[w]; tr += r2[w]; tn += r3[w]; }
        if (tc != 0.f) atomicAdd(&g_class, tc);
        if (tr != 0.f) atomicAdd(&g_coord[b], tr);
        if (tn != 0.f) atomicAdd(&g_cntf[b], tn);
    }
}

// ---- k4: forced corrections (tiny), output, reset ----
__global__ __launch_bounds__(256) void kFinal(
    const float4* __restrict__ boxes, const float2* __restrict__ cls,
    const float4* __restrict__ anchors, const float* __restrict__ gt,
    const int* __restrict__ nobj, float* __restrict__ out)
{
    const int b = blockIdx.x, tid = threadIdx.x;
    const int n = __ldg(nobj + b);

    __shared__ float sx1[NG], sy1[NG], sx2[NG], sy2[NG], ssg[NG];
    __shared__ bool  s_last;

    if (tid < NG) {
        float4 q = ((const float4*)gt)[b * NG + tid];
        float hx = q.z * 0.5f, hy = q.w * 0.5f;
        float x1 = q.x - hx, y1 = q.y - hy, x2 = q.x + hx, y2 = q.y + hy;
        sx1[tid] = x1; sy1[tid] = y1; sx2[tid] = x2; sy2[tid] = y2;
        ssg[tid] = (x2 - x1) * (y2 - y1);
    }
    __syncthreads();

    float cc = 0.f, crd = 0.f, cnt = 0.f;
    if (tid < n) {                          // forced corrections, one thread per gt
        unsigned fx = ~(unsigned)g_best[b * NG + tid];
        float4 qa = __ldg(anchors + fx);
        float sa = (qa.z - qa.x) * (qa.w - qa.y);
        unsigned w2 = 0u;
        for (int g2 = 0; g2 < n; g2++) {
            float lx = fmaxf(qa.x, sx1[g2]), ly = fmaxf(qa.y, sy1[g2]);
            float rx = fminf(qa.z, sx2[g2]), ry = fminf(qa.w, sy2[g2]);
            float w = fmaxf(rx - lx, 0.f), h = fmaxf(ry - ly, 0.f);
            float inter = w * h, u = (sa + ssg[g2]) - inter;
            if (fmaf(-0.5f, u, inter) > 0.f) w2 |= 1u << g2;
        }
        if (!((w2 >> tid) & 1u)) {          // forced pair not already counted
            float4 qb = __ldg(&boxes[b * NA + fx]);
            crd += fabsf(qb.x - sx1[tid]) + fabsf(qb.y - sy1[tid])
                 + fabsf(qb.z - sx2[tid]) + fabsf(qb.w - sy2[tid]);
            cnt += 1.f;
        }
        if (w2 == 0u) {                     // anchor was negative in global sum
            bool first = true;              // dedupe: smallest g forcing this anchor
            for (int g2 = 0; g2 < tid; g2++)
                if ((~(unsigned)g_best[b * NG + g2]) == fx) first = false;
            if (first) {
                float2 c = __ldg(&cls[b * NA + fx]);
                cc += focal(c.y) - focal(c.x);
            }
        }
    }
    if (tid < 32) {
#pragma unroll
        for (int o = 16; o; o >>= 1) {
            cc  += __shfl_down_sync(0xffffffffu, cc, o);
            crd += __shfl_down_sync(0xffffffffu, crd, o);
            cnt += __shfl_down_sync(0xffffffffu, cnt, o);
        }
        if (tid == 0) {
            if (cc != 0.f) atomicAdd(&g_class, cc);
            g_coord[b] += crd;              // single block per b owns this now
            g_cntf[b]  += cnt;
            __threadfence();
            s_last = (atomicAdd(&g_tickF, 1) == NB - 1);
        }
    }
    __syncthreads();
    if (s_last) {
        // reset scratch for next graph replay
        if (tid < NCELL) { g_hist[tid] = 0u; g_cur[tid] = 0u; }
        if (tid == 0) {
            __threadfence();
            float coord = 0.f;
#pragma unroll
            for (int bb = 0; bb < NB; bb++)
                coord += (*(volatile float*)&g_coord[bb])
                       / (4.f * (*(volatile float*)&g_cntf[bb]));
            float cl = (*(volatile float*)&g_class) * (0.01f / 8.f);
            float co = coord * (1.0f / 8.f);
            out[0] = cl + co; out[1] = cl; out[2] = co;
            g_class = 0.f; g_tickF = 0;
#pragma unroll
            for (int bb = 0; bb < NB; bb++) { g_coord[bb] = 0.f; g_cntf[bb] = 0.f; }
        }
    }
}

extern "C" void kernel_launch(void* const* d_in, const int* in_sizes, int n_in,
                              void* d_out, int out_size) {
    const float* boxes   = (const float*)d_in[0];   // [8,65536,4]
    const float* classes = (const float*)d_in[1];   // [8,65536,2]
    const float* anchors = (const float*)d_in[2];   // [65536,4] xyxy
    const float* gt      = (const float*)d_in[3];   // [8,32,4] xywh
    const int*   nobj    = (const int*)d_in[4];     // [8]
    float* out = (float*)d_out;

    kHist   <<<NA / 256, 256>>>((const float4*)anchors, (const float2*)classes);
    kScatter<<<NA / 256, 256>>>((const float4*)anchors);
    kPairs  <<<NB * NCELL, 256>>>((const float4*)boxes, (const float2*)classes,
                                  gt, nobj);
    kFinal  <<<NB, 256>>>((const float4*)boxes, (const float2*)classes,
                          (const float4*)anchors, gt, nobj, out);
}

// round 16
// speedup vs baseline: 1.6262x; 1.4577x over previous
#include <cuda_runtime.h>

#define NB 8
#define NA 65536
#define NG 32

#define AW   64                // anchors per warp
#define WPB  8                 // warps per block
#define ABLK (AW * WPB)        // 512 anchors per block
#define NCH  (NA / ABLK)       // 128 chunks per batch
#define NBLK (NCH * NB)        // 1024 blocks

typedef unsigned long long ull;

// Scratch (no allocations allowed)
__device__ float    g_pi[NB * NG * NCH];
__device__ float    g_pu[NB * NG * NCH];
__device__ unsigned g_px[NB * NG * NCH];
__device__ float    g_class;
__device__ float    g_coord[NB];
__device__ float    g_cntf[NB];
__device__ int      g_tickA[NB];
__device__ int      g_tickF;

// LG = log2(lanes per gt-group); G = 32>>LG anchors per slot, 4 slots/pass.
template <int LG>
__device__ __forceinline__ void kern_impl(
    const float* __restrict__ boxes,     // [B,A,4]
    const float* __restrict__ cls,       // [B,A,2]
    const float* __restrict__ anchors,   // [A,4] xyxy
    const float* __restrict__ gt,        // [B,G,4] xywh
    float* __restrict__ out,
    int n, int b, int chunk)
{
    constexpr int GSZ = 1 << LG;
    constexpr int G   = 32 >> LG;
    constexpr int P   = AW / G;          // passes per warp (32 or 64)
    constexpr unsigned MG = (GSZ == 32) ? 0xffffffffu : ((1u << GSZ) - 1u);

    const int tid  = threadIdx.x;
    const int lane = tid & 31, warp = tid >> 5;
    const int gl   = lane & (GSZ - 1);
    const int grp  = lane >> LG;

    __shared__ float    s_gx1[NG], s_gy1[NG], s_gx2[NG], s_gy2[NG], s_sg[NG];
    __shared__ float    s_bi[WPB][32], s_bu[WPB][32];
    __shared__ unsigned s_bx[WPB][32];
    __shared__ float    r_cls[WPB], r_crd[WPB], r_cnt[WPB];
    __shared__ unsigned sFx[NG];
    __shared__ bool     s_last;

    // ---- preamble ----
    if (tid < NG) {
        float4 q = ((const float4*)gt)[b * NG + tid];
        float hx = q.z * 0.5f, hy = q.w * 0.5f;
        float x1 = q.x - hx, y1 = q.y - hy, x2 = q.x + hx, y2 = q.y + hy;
        s_gx1[tid] = x1; s_gy1[tid] = y1; s_gx2[tid] = x2; s_gy2[tid] = y2;
        s_sg[tid]  = (x2 - x1) * (y2 - y1);
    }
    float gx1, gy1, gx2, gy2, sg;
    {
        float4 q = ((const float4*)gt)[b * NG + gl];
        float hx = q.z * 0.5f, hy = q.w * 0.5f;
        gx1 = q.x - hx; gy1 = q.y - hy; gx2 = q.x + hx; gy2 = q.y + hy;
        sg  = (gx2 - gx1) * (gy2 - gy1);
        if (gl >= n) { gx1 = 3e9f; gx2 = 3e9f; gy1 = 0.f; gy2 = 1.f; sg = 0.f; }
    }
    __syncthreads();

    const int wbase = chunk * ABLK + warp * AW;

    // phase-2 anchors for this lane: a0 and a0+G (prefetch cls; independent)
    const int a0 = wbase + (2 * gl) * G + grp;
    float2 c0 = __ldg((const float2*)cls + b * NA + a0);
    float2 c1 = __ldg((const float2*)cls + b * NA + a0 + G);

    // ---- phase 1: IoU columns + 4-slot argmax ----
    float    bi[4], bu[4];
    unsigned bx[4];
#pragma unroll
    for (int k = 0; k < 4; k++) {
        bi[k] = 0.f; bu[k] = 1.f; bx[k] = (unsigned)(wbase + k * G + grp);
    }
    unsigned c_lo = 0u, c_hi = 0u;       // per-lane column: bit p = pos(anchor p)

#pragma unroll
    for (int it = 0; it < P / 4; it++) {
#pragma unroll
        for (int k = 0; k < 4; k++) {
            const int p  = it * 4 + k;
            const int ak = wbase + p * G + grp;
            float4 q = __ldg(((const float4*)anchors) + ak);
            float sa = (q.z - q.x) * (q.w - q.y);
            float lx = fmaxf(q.x, gx1), ly = fmaxf(q.y, gy1);
            float rx = fminf(q.z, gx2), ry = fminf(q.w, gy2);
            float w = fmaxf(rx - lx, 0.f), h = fmaxf(ry - ly, 0.f);
            float inter = w * h, u = (sa + sg) - inter;
            // exact sign of inter - 0.5u (single rounding; 0.5u exact)
            bool pos = fmaf(-0.5f, u, inter) > 0.f;
            if (p < 32) { if (pos) c_lo |= (1u << p); }
            else        { if (pos) c_hi |= (1u << (p - 32)); }
            // iou > best  <=>  inter*bu > bi*u  (u,bu > 0); strict > keeps
            // earliest anchor in this slot's ascending sequence
            bool bet = inter * bu[k] > bi[k] * u;
            bi[k] = bet ? inter : bi[k];
            bu[k] = bet ? u     : bu[k];
            bx[k] = bet ? (unsigned)ak : bx[k];
        }
    }

    // any-positive word per anchor group (partitioned OR-reduce over gts)
    const unsigned mgrp = (GSZ == 32) ? 0xffffffffu : (MG << (grp * GSZ));
    unsigned any_lo = __reduce_or_sync(mgrp, c_lo);
    unsigned any_hi = (G == 1) ? __reduce_or_sync(mgrp, c_hi) : 0u;

    // ---- phase 2: class (any-word) + coord (own column vs register gt) ----
    float cls_sum, crd_sum = 0.f, cnt_sum;
    {
        const ull anyw = ((ull)any_hi << 32) | (ull)any_lo;
        const int p0 = 2 * gl;
        bool a0p = (anyw >> p0) & 1ull;
        bool a1p = (anyw >> (p0 + 1)) & 1ull;
        float pa = a0p ? c0.y : c0.x;
        float pb = a1p ? c1.y : c1.x;
        float oa = 1.f - pa, ob = 1.f - pb;
        cls_sum = oa * oa * (-__logf(pa)) + ob * ob * (-__logf(pb));

        ull colw = ((ull)c_hi << 32) | (ull)c_lo;
        cnt_sum = (float)__popcll(colw);
        while (colw) {
            int p = __ffsll((long long)colw) - 1; colw &= colw - 1;
            float4 qb = __ldg((const float4*)boxes + b * NA + wbase + p * G + grp);
            crd_sum += fabsf(qb.x - gx1) + fabsf(qb.y - gy1)
                     + fabsf(qb.z - gx2) + fabsf(qb.w - gy2);
        }
    }
#pragma unroll
    for (int off = 16; off; off >>= 1) {
        cls_sum += __shfl_down_sync(0xffffffffu, cls_sum, off);
        crd_sum += __shfl_down_sync(0xffffffffu, crd_sum, off);
        cnt_sum += __shfl_down_sync(0xffffffffu, cnt_sum, off);
    }
    if (lane == 0) { r_cls[warp] = cls_sum; r_crd[warp] = crd_sum; r_cnt[warp] = cnt_sum; }

    // argmax slot merge + deposit
    float Bi = bi[0], Bu = bu[0]; unsigned Bx = bx[0];
#pragma unroll
    for (int k = 1; k < 4; k++) {
        float A = bi[k] * Bu, C = Bi * bu[k];
        if (A > C || (A == C && bx[k] < Bx)) { Bi = bi[k]; Bu = bu[k]; Bx = bx[k]; }
    }
    s_bi[warp][lane] = Bi; s_bu[warp][lane] = Bu; s_bx[warp][lane] = Bx;
    __syncthreads();

    if (tid < GSZ) {                // one thread per g: merge warps x groups
        float Ri = 0.f, Ru = 1.f; unsigned Rx = 0xffffffffu;
#pragma unroll
        for (int w = 0; w < WPB; w++)
#pragma unroll
            for (int j = 0; j < G; j++) {
                const int l = tid + (j << LG);
                float oi = s_bi[w][l], ou = s_bu[w][l];
                unsigned ox = s_bx[w][l];
                float A = oi * Ru, C = Ri * ou;
                if (A > C || (A == C && ox < Rx)) { Ri = oi; Ru = ou; Rx = ox; }
            }
        const int p = (b * NG + tid) * NCH + chunk;
        g_pi[p] = Ri; g_pu[p] = Ru; g_px[p] = Rx;
    }
    if (tid == 0) {
        float tc = 0.f, tr = 0.f, tn = 0.f;
#pragma unroll
        for (int w = 0; w < WPB; w++) { tc += r_cls[w]; tr += r_crd[w]; tn += r_cnt[w]; }
        atomicAdd(&g_class, tc);
        atomicAdd(&g_coord[b], tr);
        atomicAdd(&g_cntf[b], tn);
    }
    __syncthreads();                // all g_pi stores + atomics done block-wide

    if (tid == 0) {
        __threadfence();
        s_last = (atomicAdd(&g_tickA[b], 1) == NCH - 1);
    }
    __syncthreads();
    if (!s_last) return;

    // ---- per-batch finalize: argmax over chunks, forced corrections ----
    {
        const int g = tid >> 3, s = tid & 7;
        const int base = (b * NG + g) * NCH;
        float Fi = 0.f, Fu = 1.f; unsigned Fx = 0xffffffffu;
#pragma unroll 4
        for (int c = s * (NCH / 8); c < (s + 1) * (NCH / 8); c++) {
            float oi = __ldcg(&g_pi[base + c]);
            float ou = __ldcg(&g_pu[base + c]);
            unsigned ox = __ldcg(&g_px[base + c]);
            float A = oi * Fu, C = Fi * ou;
            if (A > C || (A == C && ox < Fx)) { Fi = oi; Fu = ou; Fx = ox; }
        }
#pragma unroll
        for (int off = 4; off; off >>= 1) {
            float    oi = __shfl_down_sync(0xffffffffu, Fi, off, 8);
            float    ou = __shfl_down_sync(0xffffffffu, Fu, off, 8);
            unsigned ox = __shfl_down_sync(0xffffffffu, Fx, off, 8);
            float A = oi * Fu, C = Fi * ou;
            if (A > C || (A == C && ox < Fx)) { Fi = oi; Fu = ou; Fx = ox; }
        }
        if (s == 0) sFx[g] = Fx;
    }
    __syncthreads();

    float clsc = 0.f, crdc = 0.f, cntc = 0.f;
    if (tid < n) {                  // thread per valid g
        unsigned fx = sFx[tid];
        float4 qa = __ldg((const float4*)anchors + fx);
        float sa = (qa.z - qa.x) * (qa.w - qa.y);
        unsigned word = 0;
        for (int g2 = 0; g2 < n; g2++) {   // recompute this anchor's iou-mask
            float lx = fmaxf(qa.x, s_gx1[g2]), ly = fmaxf(qa.y, s_gy1[g2]);
            float rx = fminf(qa.z, s_gx2[g2]), ry = fminf(qa.w, s_gy2[g2]);
            float w = fmaxf(rx - lx, 0.f), h = fmaxf(ry - ly, 0.f);
            float inter = w * h, u = (sa + s_sg[g2]) - inter;
            if (fmaf(-0.5f, u, inter) > 0.f) word |= 1u << g2;
        }
        if (!((word >> tid) & 1)) { // forced pair not already counted
            float4 qb = __ldg((const float4*)boxes + b * NA + fx);
            crdc = fabsf(qb.x - s_gx1[tid]) + fabsf(qb.y - s_gy1[tid])
                 + fabsf(qb.z - s_gx2[tid]) + fabsf(qb.w - s_gy2[tid]);
            cntc = 1.f;
        }
        if (word == 0) {            // anchor counted as negative in phase 2
            bool first = true;      // dedupe: smallest g forcing this anchor
            for (int g2 = 0; g2 < tid; g2++) if (sFx[g2] == fx) first = false;
            if (first) {
                float2 cc = __ldg((const float2*)cls + b * NA + fx);
                float o1 = 1.f - cc.y, o0 = 1.f - cc.x;
                clsc = o1 * o1 * (-__logf(cc.y)) - o0 * o0 * (-__logf(cc.x));
            }
        }
    }
    if (tid < 32) {
#pragma unroll
        for (int off = 16; off; off >>= 1) {
            clsc += __shfl_down_sync(0xffffffffu, clsc, off);
            crdc += __shfl_down_sync(0xffffffffu, crdc, off);
            cntc += __shfl_down_sync(0xffffffffu, cntc, off);
        }
    }
    if (tid == 0) {
        atomicAdd(&g_class, clsc);
        atomicAdd(&g_coord[b], crdc);
        atomicAdd(&g_cntf[b], cntc);
        g_tickA[b] = 0;
        __threadfence();
        if (atomicAdd(&g_tickF, 1) == NB - 1) {      // last batch: emit output
            __threadfence();
            float coord = 0.f;
#pragma unroll
            for (int bb = 0; bb < NB; bb++)
                coord += (*(volatile float*)&g_coord[bb])
                       / (4.f * (*(volatile float*)&g_cntf[bb]));
            float cl = (*(volatile float*)&g_class) * (0.01f / 8.f);
            float co = coord * (1.0f / 8.f);
            out[0] = cl + co; out[1] = cl; out[2] = co;
            // reset for next graph replay
            g_class = 0.f; g_tickF = 0;
#pragma unroll
            for (int bb = 0; bb < NB; bb++) { g_coord[bb] = 0.f; g_cntf[bb] = 0.f; }
        }
    }
}

__global__ __launch_bounds__(256, 6) void kFused(
    const float* __restrict__ boxes, const float* __restrict__ cls,
    const float* __restrict__ anchors, const float* __restrict__ gt,
    const int* __restrict__ nobj, float* __restrict__ out)
{
    const int b = blockIdx.x & (NB - 1), chunk = blockIdx.x >> 3;
    const int n = __ldg(nobj + b);
    if (n <= 16)
        kern_impl<4>(boxes, cls, anchors, gt, out, n, b, chunk);
    else
        kern_impl<5>(boxes, cls, anchors, gt, out, n, b, chunk);
}

extern "C" void kernel_launch(void* const* d_in, const int* in_sizes, int n_in,
                              void* d_out, int out_size) {
    const float* boxes   = (const float*)d_in[0];   // [8,65536,4]
    const float* classes = (const float*)d_in[1];   // [8,65536,2]
    const float* anchors = (const float*)d_in[2];   // [65536,4] xyxy
    const float* gt      = (const float*)d_in[3];   // [8,32,4] xywh
    const int*   nobj    = (const int*)d_in[4];     // [8]
    float* out = (float*)d_out;

    kFused<<<NBLK, 256>>>(boxes, classes, anchors, gt, nobj, out);
}